// round 13
// baseline (speedup 1.0000x reference)
#include <cuda_runtime.h>
#include <cstdint>

// SpatialTransformer bilinear flow warp — sliding-window smem ring.
// src: [B,H,W,1] f32, flow: [B,H,W,2] f32, out: [B,H,W,1] f32. B=32,H=W=768.
//
// Each block: one image band, full width x 96 rows. A 64-row ring buffer
// (768x64 f32 = 196KB smem) slides down the band:
//   prologue: stage rows [start-16, start+32)          (clamped)
//   chunk i (c = start+16i): stage rows [c+32, c+48) while computing
//   output rows [c, c+16) from the ring; one __syncthreads per chunk.
// Ring disjointness: reads [c-16, c+31] & 63 vs writes [c+32, c+47] & 63
// = [c-32, c-17] & 63 -> no overlap.
// Gathers: 4x LDS (bank = x & 31, ~2-way conflicts), no L1tex gather
// wavefronts, src amplification 1.33x (band halo) instead of R7's 2.7x.
// Fast path valid iff ix0 in [0,766], iy0 in [0,766] AND iy0 in
// [c-16, c+30] (window): else exact global clamped gather (5-sigma rare).

#define BB 32
#define HH 768
#define WW 768
#define HW (HH * WW)

#define BAND 96
#define CH 16
#define NCHUNK (BAND / CH)     // 6
#define RING 64
#define THREADS 1024

// stage 16 global rows [g0, g0+16) into ring slots (g&63), row-clamped
__device__ __forceinline__ void stage16(float* ring, const float* img, int g0)
{
    const int tid  = threadIdx.x;
    const int w    = tid >> 5;
    const int lane = tid & 31;
    const int row  = w >> 1;                 // 0..15
    const int half = (w & 1) * 96;           // float4 offset within row (192 f4/row)
    const int gy   = min(max(g0 + row, 0), HH - 1);
    const int slot = (g0 + row) & (RING - 1);

    const float4* s = reinterpret_cast<const float4*>(img + gy * WW);
    float4*       d = reinterpret_cast<float4*>(ring + slot * WW);
    #pragma unroll
    for (int k = 0; k < 3; k++)
        d[half + k * 32 + lane] = s[half + k * 32 + lane];
}

__global__ __launch_bounds__(THREADS, 1) void warp_kernel(
    const float* __restrict__ src,
    const float* __restrict__ flow,
    float* __restrict__ out)
{
    extern __shared__ float ring[];          // RING * WW floats = 196608 B

    const int b     = blockIdx.y;
    const int start = blockIdx.x * BAND;
    const float* img = src + b * HW;

    // ---- prologue: rows [start-16, start+32) ----
    stage16(ring, img, start - 16);
    stage16(ring, img, start);
    stage16(ring, img, start + 16);
    __syncthreads();

    const int tid   = threadIdx.x;
    const int w     = tid >> 5;
    const int lane  = tid & 31;
    const int yoff  = w >> 1;                 // row within chunk (0..15)
    const int xbase = (w & 1) * 384 + lane;   // x start for this warp-half

    for (int i = 0; i < NCHUNK; i++) {
        const int c = start + i * CH;

        // stage next chunk's new rows (slots disjoint from current reads)
        if (i + 1 < NCHUNK) stage16(ring, img, c + 32);

        const int y    = c + yoff;
        const int lo   = c - 16;              // window low (may be <0)
        const int rowb = (b * HH + y) * WW;
        const float yf = (float)y;

        #pragma unroll 4
        for (int j = 0; j < 12; j++) {
            const int xg  = xbase + j * 32;
            const int pix = rowb + xg;

            const float2 f = *reinterpret_cast<const float2*>(flow + (size_t)pix * 2);

            const float gx = (float)xg + f.x;
            const float gy = yf + f.y;

            const float x0f = floorf(gx);
            const float y0f = floorf(gy);
            const float x1f = x0f + 1.0f;
            const float y1f = y0f + 1.0f;

            // weights from UNCLIPPED corners — exact reference formulation
            const float dx1 = x1f - gx;
            const float dx0 = gx - x0f;
            const float dy1 = y1f - gy;
            const float dy0 = gy - y0f;

            const float wa = dx1 * dy1;
            const float wb = dx0 * dy1;
            const float wc = dx1 * dy0;
            const float wd = dx0 * dy0;

            const int ix0 = (int)x0f;
            const int iy0 = (int)y0f;

            float va, vb, vc, vd;
            // fast: clamps identity AND both rows inside the ring window
            if (((unsigned)ix0 <= (WW - 2)) &
                ((unsigned)iy0 <= (HH - 2)) &
                ((unsigned)(iy0 - lo) <= 46u)) {
                const int s0 = (iy0 & (RING - 1)) * WW + ix0;
                const int s1 = ((iy0 + 1) & (RING - 1)) * WW + ix0;
                va = ring[s0];
                vb = ring[s0 + 1];
                vc = ring[s1];
                vd = ring[s1 + 1];
            } else {
                // exact reference slow path (clamped global gather)
                const int xi0 = (int)fminf(fmaxf(x0f, 0.0f), (float)(WW - 1));
                const int xi1 = (int)fminf(fmaxf(x1f, 0.0f), (float)(WW - 1));
                const int yi0 = (int)fminf(fmaxf(y0f, 0.0f), (float)(HH - 1));
                const int yi1 = (int)fminf(fmaxf(y1f, 0.0f), (float)(HH - 1));
                const int g0 = yi0 * WW;
                const int g1 = yi1 * WW;
                va = __ldg(img + g0 + xi0);
                vb = __ldg(img + g0 + xi1);
                vc = __ldg(img + g1 + xi0);
                vd = __ldg(img + g1 + xi1);
            }

            out[pix] = wa * va + wb * vb + wc * vc + wd * vd;
        }

        __syncthreads();
    }
}

extern "C" void kernel_launch(void* const* d_in, const int* in_sizes, int n_in,
                              void* d_out, int out_size)
{
    const float* src  = (const float*)d_in[0];
    const float* flow = (const float*)d_in[1];
    float* out = (float*)d_out;

    const int smem = RING * WW * sizeof(float);   // 196608
    static bool configured = false;
    // idempotent attribute set (host-side, not a stream op; capture-safe)
    cudaFuncSetAttribute(warp_kernel,
                         cudaFuncAttributeMaxDynamicSharedMemorySize, smem);

    dim3 grid(HH / BAND, BB);    // (8, 32) = 256 blocks
    warp_kernel<<<grid, THREADS, smem>>>(src, flow, out);
    (void)configured;
}

// round 14
// speedup vs baseline: 1.5237x; 1.5237x over previous
#include <cuda_runtime.h>
#include <cstdint>

// SpatialTransformer bilinear flow warp — R8 skeleton + conditional pair-load.
// src:  [B,H,W,1] f32,  flow: [B,H,W,2] f32,  out: [B,H,W,1] f32
// B=32, H=768, W=768.
//
// Plateau model: L1tex sector-visit bound; va/vb (x0, x0+1) revisit ~90% of
// the same sectors as two separate gathers. Fix: one aligned float2 load at
// e = x0 & ~1 covers both corners when x0 even; only odd lanes (~50%,
// predicated) issue a second scalar load for x0+1 = e+2. Same for row y0+1.
// R12's mistake (unconditional second wide load) is avoided.
// Values/weights bit-identical to the reference; clamped slow path intact.
// Layout: 32x16 tile / 128-thr block, warp = 32 consecutive x, 4-row strip.

#define BB 32
#define HH 768
#define WW 768
#define HW (HH * WW)

__global__ __launch_bounds__(128) void warp_kernel(
    const float* __restrict__ src,
    const float* __restrict__ flow,
    float* __restrict__ out)
{
    const int tx = threadIdx.x;
    const int xg = blockIdx.x * 32 + (tx & 31);       // global x
    const int yb = blockIdx.y * 16 + (tx >> 5) * 4;   // first of 4 rows
    const int b  = blockIdx.z;

    const float* img = src + b * HW;
    const float  xgf = (float)xg;

    #pragma unroll
    for (int r = 0; r < 4; r++) {
        const int y   = yb + r;
        const int pix = (b * HH + y) * WW + xg;

        const float2 f = *reinterpret_cast<const float2*>(flow + (size_t)pix * 2);

        const float gx = xgf + f.x;
        const float gy = (float)y + f.y;

        const float x0f = floorf(gx);
        const float y0f = floorf(gy);
        const float x1f = x0f + 1.0f;
        const float y1f = y0f + 1.0f;

        // weights from UNCLIPPED corners — exact reference formulation
        const float dx1 = x1f - gx;
        const float dx0 = gx - x0f;
        const float dy1 = y1f - gy;
        const float dy0 = gy - y0f;

        const float wa = dx1 * dy1;
        const float wb = dx0 * dy1;
        const float wc = dx1 * dy0;
        const float wd = dx0 * dy0;

        const int ix0 = (int)x0f;
        const int iy0 = (int)y0f;

        float va, vb, vc, vd;
        // fast iff ix0 in [0, W-2] and iy0 in [0, H-2]: clamps are identity
        if (((unsigned)ix0 < (WW - 1)) & ((unsigned)iy0 < (HH - 1))) {
            const int  e   = ix0 & ~1;       // even, 8B-aligned
            const bool odd = (ix0 & 1);
            const float* p0 = img + iy0 * WW + e;

            const float2 lo0 = __ldg(reinterpret_cast<const float2*>(p0));
            const float2 lo1 = __ldg(reinterpret_cast<const float2*>(p0 + WW));

            float hb0 = 0.0f, hb1 = 0.0f;
            if (odd) {                       // predicated: ~50% lanes
                hb0 = __ldg(p0 + 2);         // x0+1 = e+2
                hb1 = __ldg(p0 + WW + 2);
            }

            va = odd ? lo0.y : lo0.x;
            vb = odd ? hb0   : lo0.y;
            vc = odd ? lo1.y : lo1.x;
            vd = odd ? hb1   : lo1.y;
        } else {
            // exact reference slow path (clamped indices)
            const int xi0 = (int)fminf(fmaxf(x0f, 0.0f), (float)(WW - 1));
            const int xi1 = (int)fminf(fmaxf(x1f, 0.0f), (float)(WW - 1));
            const int yi0 = (int)fminf(fmaxf(y0f, 0.0f), (float)(HH - 1));
            const int yi1 = (int)fminf(fmaxf(y1f, 0.0f), (float)(HH - 1));
            const int g0 = yi0 * WW;
            const int g1 = yi1 * WW;
            va = __ldg(img + g0 + xi0);
            vb = __ldg(img + g0 + xi1);
            vc = __ldg(img + g1 + xi0);
            vd = __ldg(img + g1 + xi1);
        }

        out[pix] = wa * va + wb * vb + wc * vc + wd * vd;
    }
}

extern "C" void kernel_launch(void* const* d_in, const int* in_sizes, int n_in,
                              void* d_out, int out_size)
{
    const float* src  = (const float*)d_in[0];
    const float* flow = (const float*)d_in[1];
    float* out = (float*)d_out;

    dim3 grid(WW / 32, HH / 16, BB);   // (24, 48, 32)
    warp_kernel<<<grid, 128>>>(src, flow, out);
}

// round 15
// speedup vs baseline: 1.8039x; 1.1839x over previous
#include <cuda_runtime.h>
#include <cstdint>

// SpatialTransformer bilinear flow warp — FINAL (measured-best, R5 config).
// src:  [B,H,W,1] f32,  flow: [B,H,W,2] f32,  out: [B,H,W,1] f32
// B=32, H=768, W=768.
//
// Operating point established over 10 variants:
//   - 128-thread blocks (4 warps), tile 32x16, ~90% occupancy, 32 regs
//   - lane -> 32 consecutive x  => flow/out coalesced; gathers span minimal
//     x-lines per warp
//   - warp -> 4-row vertical strip => bilinear row-halo reuse in L1
//   - plain scalar __ldg gathers: L1tex wavefront cost is per line-visit;
//     wide/predicated/smem variants all measured slower.
// The kernel sits at the L1tex structural limit (~10 distinct lines per
// gather instruction from random per-lane flow.y); DRAM traffic is at the
// mandatory ~300MB floor.

#define BB 32
#define HH 768
#define WW 768
#define HW (HH * WW)

__global__ __launch_bounds__(128) void warp_kernel(
    const float* __restrict__ src,
    const float* __restrict__ flow,
    float* __restrict__ out)
{
    const int tx = threadIdx.x;
    const int xg = blockIdx.x * 32 + (tx & 31);       // global x
    const int yb = blockIdx.y * 16 + (tx >> 5) * 4;   // first of 4 rows
    const int b  = blockIdx.z;

    const float* img = src + b * HW;
    const float  xgf = (float)xg;

    #pragma unroll
    for (int r = 0; r < 4; r++) {
        const int y   = yb + r;
        const int pix = (b * HH + y) * WW + xg;

        const float2 f = *reinterpret_cast<const float2*>(flow + (size_t)pix * 2);

        const float gx = xgf + f.x;
        const float gy = (float)y + f.y;

        const float x0f = floorf(gx);
        const float y0f = floorf(gy);
        const float x1f = x0f + 1.0f;
        const float y1f = y0f + 1.0f;

        // bilinear weights from UNCLIPPED corners (matches reference)
        const float dx1 = x1f - gx;
        const float dx0 = gx - x0f;
        const float dy1 = y1f - gy;
        const float dy0 = gy - y0f;

        const float wa = dx1 * dy1;
        const float wb = dx0 * dy1;
        const float wc = dx1 * dy0;
        const float wd = dx0 * dy0;

        // clipped integer indices (exact reference semantics)
        const int xi0 = (int)fminf(fmaxf(x0f, 0.0f), (float)(WW - 1));
        const int xi1 = (int)fminf(fmaxf(x1f, 0.0f), (float)(WW - 1));
        const int yi0 = (int)fminf(fmaxf(y0f, 0.0f), (float)(HH - 1));
        const int yi1 = (int)fminf(fmaxf(y1f, 0.0f), (float)(HH - 1));

        const int r0 = yi0 * WW;
        const int r1 = yi1 * WW;

        const float va = __ldg(img + r0 + xi0);
        const float vb = __ldg(img + r0 + xi1);
        const float vc = __ldg(img + r1 + xi0);
        const float vd = __ldg(img + r1 + xi1);

        out[pix] = wa * va + wb * vb + wc * vc + wd * vd;
    }
}

extern "C" void kernel_launch(void* const* d_in, const int* in_sizes, int n_in,
                              void* d_out, int out_size)
{
    const float* src  = (const float*)d_in[0];
    const float* flow = (const float*)d_in[1];
    float* out = (float*)d_out;

    dim3 grid(WW / 32, HH / 16, BB);   // (24, 48, 32)
    warp_kernel<<<grid, 128>>>(src, flow, out);
}